// round 12
// baseline (speedup 1.0000x reference)
#include <cuda_runtime.h>
#include <cstdint>

#define N_NODES 8192
#define FEAT    256

// ---------------------------------------------------------------------------
// Device scratch
// ---------------------------------------------------------------------------
__device__ __align__(128) float g_d[N_NODES];             // rsqrt degree
__device__ __align__(128) float g_supp[N_NODES * FEAT];   // d_k*(X W), row-major [k][n] (fixup)
__device__ __align__(128) float g_suppT[FEAT * N_NODES];  // same, transposed [n][k] (main GEMM B)
__device__ __align__(128) float g_part[2 * N_NODES * FEAT];  // split-K partials

// ---------------------------------------------------------------------------
// helpers
// ---------------------------------------------------------------------------
__device__ __forceinline__ uint32_t smem_to_u32(const void* p) {
    uint32_t a;
    asm("{ .reg .u64 t; cvta.to.shared.u64 t, %1; cvt.u32.u64 %0, t; }" : "=r"(a) : "l"(p));
    return a;
}
#define CP_ASYNC_CG(smem, gptr) \
    asm volatile("cp.async.cg.shared.global [%0], [%1], 16;" :: "r"((uint32_t)(smem)), "l"(gptr) : "memory")
#define CP_COMMIT() asm volatile("cp.async.commit_group;" ::: "memory")
#define CP_WAIT0()  asm volatile("cp.async.wait_group 0;" ::: "memory")

#define LDSM_X4(r0, r1, r2, r3, addr) \
    asm volatile("ldmatrix.sync.aligned.m8n8.x4.shared.b16 {%0,%1,%2,%3}, [%4];" \
                 : "=r"(r0), "=r"(r1), "=r"(r2), "=r"(r3) : "r"(addr))

__device__ __forceinline__ void mma_tf32(float* c, const uint32_t* a, const uint32_t* b) {
    asm volatile(
        "mma.sync.aligned.m16n8k8.row.col.f32.tf32.tf32.f32 "
        "{%0,%1,%2,%3}, {%4,%5,%6,%7}, {%8,%9}, {%0,%1,%2,%3};"
        : "+f"(c[0]), "+f"(c[1]), "+f"(c[2]), "+f"(c[3])
        : "r"(a[0]), "r"(a[1]), "r"(a[2]), "r"(a[3]), "r"(b[0]), "r"(b[1]));
}

// ---------------------------------------------------------------------------
// Kernel 1: d[i] = rsqrt(1 + rowsum(adj))
// ---------------------------------------------------------------------------
__global__ __launch_bounds__(256)
void rowsum_rsqrt_kernel(const float* __restrict__ adj) {
    const int row = blockIdx.x;
    const float4* rp = reinterpret_cast<const float4*>(adj + (size_t)row * N_NODES);
    float s = 0.0f;
    #pragma unroll 4
    for (int i = threadIdx.x; i < N_NODES / 4; i += blockDim.x) {
        float4 v = __ldg(rp + i);
        s += (v.x + v.y) + (v.z + v.w);
    }
    #pragma unroll
    for (int o = 16; o > 0; o >>= 1) s += __shfl_down_sync(0xffffffffu, s, o);
    __shared__ float red[8];
    const int lane = threadIdx.x & 31;
    const int w = threadIdx.x >> 5;
    if (lane == 0) red[w] = s;
    __syncthreads();
    if (w == 0) {
        s = (lane < 8) ? red[lane] : 0.0f;
        #pragma unroll
        for (int o = 4; o > 0; o >>= 1) s += __shfl_down_sync(0xffffffffu, s, o);
        if (lane == 0) g_d[row] = rsqrtf(s + 1.0f);
    }
}

// ---------------------------------------------------------------------------
// Kernel 2: g_supp / g_suppT = d[k] * (input @ weight)   (both layouts)
// ---------------------------------------------------------------------------
#define BM 128
#define BN 128
#define BK 16
#define TM 8
#define TN 8

__global__ __launch_bounds__(256, 2)
void small_gemm_kernel(const float* __restrict__ A, const float* __restrict__ B) {
    __shared__ float As[BK][BM];
    __shared__ float Bs[BK][BN];
    const int tid = threadIdx.x;
    const int rowBase = blockIdx.y * BM;
    const int colBase = blockIdx.x * BN;
    const int ty = tid >> 4, tx = tid & 15;
    const int aRow = tid >> 2, aCol = (tid & 3) << 2;
    const int bRow = tid >> 5, bCol = (tid & 31) << 2;
    const int K = FEAT;

    float acc[TM][TN];
    #pragma unroll
    for (int m = 0; m < TM; m++)
        #pragma unroll
        for (int n = 0; n < TN; n++) acc[m][n] = 0.0f;

    for (int k0 = 0; k0 < K; k0 += BK) {
        #pragma unroll
        for (int r = 0; r < BM; r += 64) {
            float4 v = *reinterpret_cast<const float4*>(A + (size_t)(rowBase + aRow + r) * K + (k0 + aCol));
            As[aCol + 0][aRow + r] = v.x; As[aCol + 1][aRow + r] = v.y;
            As[aCol + 2][aRow + r] = v.z; As[aCol + 3][aRow + r] = v.w;
        }
        #pragma unroll
        for (int r = 0; r < BK; r += 8)
            *reinterpret_cast<float4*>(&Bs[bRow + r][bCol]) =
                *reinterpret_cast<const float4*>(B + (size_t)(k0 + bRow + r) * FEAT + (colBase + bCol));
        __syncthreads();
        #pragma unroll
        for (int k = 0; k < BK; k++) {
            float a[TM], b[TN];
            *reinterpret_cast<float4*>(&a[0]) = *reinterpret_cast<const float4*>(&As[k][ty * TM]);
            *reinterpret_cast<float4*>(&a[4]) = *reinterpret_cast<const float4*>(&As[k][ty * TM + 4]);
            *reinterpret_cast<float4*>(&b[0]) = *reinterpret_cast<const float4*>(&Bs[k][tx * TN]);
            *reinterpret_cast<float4*>(&b[4]) = *reinterpret_cast<const float4*>(&Bs[k][tx * TN + 4]);
            #pragma unroll
            for (int m = 0; m < TM; m++)
                #pragma unroll
                for (int n = 0; n < TN; n++) acc[m][n] = fmaf(a[m], b[n], acc[m][n]);
        }
        __syncthreads();
    }

    // fold d, write row-major + transposed copies
    float dv[TM];
    #pragma unroll
    for (int m = 0; m < TM; m++) dv[m] = g_d[rowBase + ty * TM + m];

    #pragma unroll
    for (int m = 0; m < TM; m++) {
        const int gr = rowBase + ty * TM + m;
        #pragma unroll
        for (int n4 = 0; n4 < TN; n4 += 4) {
            const int gc = colBase + tx * TN + n4;
            float4 o;
            o.x = dv[m] * acc[m][n4 + 0]; o.y = dv[m] * acc[m][n4 + 1];
            o.z = dv[m] * acc[m][n4 + 2]; o.w = dv[m] * acc[m][n4 + 3];
            *reinterpret_cast<float4*>(g_supp + (size_t)gr * FEAT + gc) = o;
        }
    }
    const int gr0 = rowBase + ty * TM;
    #pragma unroll
    for (int n = 0; n < TN; n++) {
        const int gc = colBase + tx * TN + n;
        float4 t0, t1;
        t0.x = dv[0] * acc[0][n]; t0.y = dv[1] * acc[1][n];
        t0.z = dv[2] * acc[2][n]; t0.w = dv[3] * acc[3][n];
        t1.x = dv[4] * acc[4][n]; t1.y = dv[5] * acc[5][n];
        t1.z = dv[6] * acc[6][n]; t1.w = dv[7] * acc[7][n];
        *reinterpret_cast<float4*>(g_suppT + (size_t)gc * N_NODES + gr0)     = t0;
        *reinterpret_cast<float4*>(g_suppT + (size_t)gc * N_NODES + gr0 + 4) = t1;
    }
}

// ---------------------------------------------------------------------------
// Kernel 3: partial[split] = adj[:, kr] @ suppd[kr, :]
// TF32 mma.sync m16n8k8, CTA 128x256, 8 warps (64x64), split-K=2, KT=64,
// 2-stage double buffer, one barrier/stage, ldmatrix fragment loads.
// A smem: [128 rows][SA] m-major; B smem: [256 n-rows][SBT] n-major.
// ---------------------------------------------------------------------------
#define SA  68                                 // A row stride (floats); 4r%32 spans banks
#define SBT 68                                 // B (transposed) row stride
#define KT  64
#define STAGE_FLOATS (128 * SA + 256 * SBT)    // 8704 + 17408 = 26112
#define STAGE_BYTES  (STAGE_FLOATS * 4)        // 104448
#define NSTAGES 2
#define MAIN_SMEM (NSTAGES * STAGE_BYTES)      // 208896
#define KSPLIT (N_NODES / 2)                   // 4096
#define NITER (KSPLIT / KT)                    // 64

__global__ __launch_bounds__(256, 1)
void gcn_main_gemm(const float* __restrict__ adj) {
    extern __shared__ float smem[];
    const uint32_t sb_u32 = smem_to_u32(smem);

    const int tid = threadIdx.x;
    const int wid = tid >> 5;
    const int lane = tid & 31;
    const int gid = lane >> 2;
    const int tig = lane & 3;
    const int wm = wid >> 2;        // 0..1
    const int wn = wid & 3;         // 0..3

    const int mBase = blockIdx.y * 128;
    const int split = blockIdx.x;

    const float* Abase = adj + (size_t)mBase * N_NODES + (size_t)split * KSPLIT;
    const float* Bbase = g_suppT + (size_t)split * KSPLIT;   // row n: + n*N_NODES

    // ldmatrix per-thread byte offsets (within a stage slot)
    const uint32_t aFragOff = (uint32_t)(wm * 64 + (lane & 15)) * (SA * 4) + ((lane >> 4) << 4);
    const uint32_t bFragOff = (uint32_t)(128 * SA * 4)
                            + (uint32_t)(wn * 64 + (lane & 15)) * (SBT * 4) + ((lane >> 4) << 4);

    float acc[4][8][4];
    #pragma unroll
    for (int mt = 0; mt < 4; mt++)
        #pragma unroll
        for (int nt = 0; nt < 8; nt++)
            #pragma unroll
            for (int c = 0; c < 4; c++) acc[mt][nt][c] = 0.0f;

    auto load_stage = [&](int s) {
        const int slot = s & (NSTAGES - 1);
        const uint32_t a_s = sb_u32 + slot * STAGE_BYTES;
        const uint32_t b_s = a_s + 128 * SA * 4;
        const float* ag = Abase + s * KT;
        const float* bg = Bbase + s * KT;
        #pragma unroll
        for (int i = 0; i < 8; i++) {            // A: 128r x 64k = 2048 granules
            const int g = tid + i * 256;
            const int r = g >> 4, q = g & 15;
            CP_ASYNC_CG(a_s + (r * SA + q * 4) * 4, ag + (size_t)r * N_NODES + q * 4);
        }
        #pragma unroll
        for (int i = 0; i < 16; i++) {           // B: 256n x 64k = 4096 granules
            const int g = tid + i * 256;
            const int n = g >> 4, q = g & 15;
            CP_ASYNC_CG(b_s + (n * SBT + q * 4) * 4, bg + (size_t)n * N_NODES + q * 4);
        }
    };

    load_stage(0); CP_COMMIT();

    for (int s = 0; s < NITER; s++) {
        CP_WAIT0();
        __syncthreads();

        if (s + 1 < NITER) { load_stage(s + 1); CP_COMMIT(); }

        const int slot = s & (NSTAGES - 1);
        const uint32_t a_s = sb_u32 + slot * STAGE_BYTES;

        #pragma unroll
        for (int k8 = 0; k8 < KT / 8; k8++) {
            const uint32_t kkb = k8 * 8 * 4;   // byte offset of k8 group
            uint32_t a[4][4], b[8][2];
            #pragma unroll
            for (int mt = 0; mt < 4; mt++) {
                LDSM_X4(a[mt][0], a[mt][1], a[mt][2], a[mt][3],
                        a_s + aFragOff + (uint32_t)(mt * 16 * SA * 4) + kkb);
            }
            #pragma unroll
            for (int j = 0; j < 4; j++) {
                LDSM_X4(b[2 * j][0], b[2 * j + 1][0], b[2 * j][1], b[2 * j + 1][1],
                        a_s + bFragOff + (uint32_t)(j * 16 * SBT * 4) + kkb);
            }
            #pragma unroll
            for (int mt = 0; mt < 4; mt++)
                #pragma unroll
                for (int nt = 0; nt < 8; nt++)
                    mma_tf32(acc[mt][nt], a[mt], b[nt]);
        }
    }

    // write raw partials
    float* dst = g_part + (size_t)split * N_NODES * FEAT;
    #pragma unroll
    for (int mt = 0; mt < 4; mt++) {
        const int r0 = mBase + wm * 64 + mt * 16 + gid;
        const int r1 = r0 + 8;
        #pragma unroll
        for (int nt = 0; nt < 8; nt++) {
            const int col = wn * 64 + nt * 8 + tig * 2;
            float2 o0, o1;
            o0.x = acc[mt][nt][0]; o0.y = acc[mt][nt][1];
            o1.x = acc[mt][nt][2]; o1.y = acc[mt][nt][3];
            *reinterpret_cast<float2*>(dst + (size_t)r0 * FEAT + col) = o0;
            *reinterpret_cast<float2*>(dst + (size_t)r1 * FEAT + col) = o1;
        }
    }
}

// ---------------------------------------------------------------------------
// Kernel 4: fixup  out = d_i*(p0 + p1 + suppd[i,:]) + bias
// ---------------------------------------------------------------------------
__global__ __launch_bounds__(256)
void fixup_kernel(float* __restrict__ out, const float* __restrict__ bias) {
    const size_t i = (size_t)blockIdx.x * 256 + threadIdx.x;
    const size_t row = i >> 6;
    const int c4 = (int)(i & 63);
    const float d = g_d[row];
    const float4 p0 = *reinterpret_cast<const float4*>(g_part + row * FEAT + c4 * 4);
    const float4 p1 = *reinterpret_cast<const float4*>(g_part + (size_t)N_NODES * FEAT + row * FEAT + c4 * 4);
    const float4 sv = *reinterpret_cast<const float4*>(g_supp + row * FEAT + c4 * 4);
    const float4 bv = *reinterpret_cast<const float4*>(bias + c4 * 4);
    float4 o;
    o.x = fmaf(d, p0.x + p1.x + sv.x, bv.x);
    o.y = fmaf(d, p0.y + p1.y + sv.y, bv.y);
    o.z = fmaf(d, p0.z + p1.z + sv.z, bv.z);
    o.w = fmaf(d, p0.w + p1.w + sv.w, bv.w);
    *reinterpret_cast<float4*>(out + row * FEAT + c4 * 4) = o;
}

// ---------------------------------------------------------------------------
extern "C" void kernel_launch(void* const* d_in, const int* in_sizes, int n_in,
                              void* d_out, int out_size) {
    const float* input  = (const float*)d_in[0];   // [8192, 256]
    const float* adj    = (const float*)d_in[1];   // [8192, 8192]
    const float* weight = (const float*)d_in[2];   // [256, 256]
    const float* bias   = (const float*)d_in[3];   // [256]
    float* out = (float*)d_out;

    cudaFuncSetAttribute(gcn_main_gemm, cudaFuncAttributeMaxDynamicSharedMemorySize, MAIN_SMEM);

    rowsum_rsqrt_kernel<<<N_NODES, 256>>>(adj);
    {
        dim3 grid(FEAT / BN, N_NODES / BM);
        small_gemm_kernel<<<grid, 256>>>(input, weight);
    }
    {
        dim3 grid(2, N_NODES / 128);   // (split, mtile) = 128 CTAs
        gcn_main_gemm<<<grid, 256, MAIN_SMEM>>>(adj);
    }
    fixup_kernel<<<(N_NODES * FEAT / 4) / 256, 256>>>(out, bias);
}

// round 13
// speedup vs baseline: 1.2182x; 1.2182x over previous
#include <cuda_runtime.h>
#include <cstdint>

#define N_NODES 8192
#define FEAT    256

// ---------------------------------------------------------------------------
// Device scratch
// ---------------------------------------------------------------------------
__device__ __align__(128) float g_d[N_NODES];            // rsqrt degree
__device__ __align__(128) float g_supp[N_NODES * FEAT];  // d_k * (input @ weight)
__device__ __align__(128) float g_part[2 * N_NODES * FEAT];  // split-K partials

// ---------------------------------------------------------------------------
// helpers
// ---------------------------------------------------------------------------
__device__ __forceinline__ uint32_t smem_to_u32(const void* p) {
    uint32_t a;
    asm("{ .reg .u64 t; cvta.to.shared.u64 t, %1; cvt.u32.u64 %0, t; }" : "=r"(a) : "l"(p));
    return a;
}
#define CP_ASYNC_CG(smem, gptr) \
    asm volatile("cp.async.cg.shared.global [%0], [%1], 16;" :: "r"((uint32_t)(smem)), "l"(gptr) : "memory")
#define CP_COMMIT() asm volatile("cp.async.commit_group;" ::: "memory")
#define CP_WAIT0()  asm volatile("cp.async.wait_group 0;" ::: "memory")

__device__ __forceinline__ void mma_tf32(float* c, const uint32_t* a, const uint32_t* b) {
    asm volatile(
        "mma.sync.aligned.m16n8k8.row.col.f32.tf32.tf32.f32 "
        "{%0,%1,%2,%3}, {%4,%5,%6,%7}, {%8,%9}, {%0,%1,%2,%3};"
        : "+f"(c[0]), "+f"(c[1]), "+f"(c[2]), "+f"(c[3])
        : "r"(a[0]), "r"(a[1]), "r"(a[2]), "r"(a[3]), "r"(b[0]), "r"(b[1]));
}

// shared GEMM geometry (both tensor kernels)
#define SA 68                                  // A smem row stride (floats)
#define SB 264                                 // B smem row stride (floats)
#define KT 64
#define STAGE_FLOATS (128 * SA + KT * SB)      // 25600
#define STAGE_BYTES  (STAGE_FLOATS * 4)        // 102400
#define NSTAGES 2
#define MAIN_SMEM (NSTAGES * STAGE_BYTES)      // 204800

// ---------------------------------------------------------------------------
// Kernel 1: d[i] = rsqrt(1 + rowsum(adj))
// ---------------------------------------------------------------------------
__global__ __launch_bounds__(256)
void rowsum_rsqrt_kernel(const float* __restrict__ adj) {
    const int row = blockIdx.x;
    const float4* rp = reinterpret_cast<const float4*>(adj + (size_t)row * N_NODES);
    float s = 0.0f;
    #pragma unroll 4
    for (int i = threadIdx.x; i < N_NODES / 4; i += blockDim.x) {
        float4 v = __ldg(rp + i);
        s += (v.x + v.y) + (v.z + v.w);
    }
    #pragma unroll
    for (int o = 16; o > 0; o >>= 1) s += __shfl_down_sync(0xffffffffu, s, o);
    __shared__ float red[8];
    const int lane = threadIdx.x & 31;
    const int w = threadIdx.x >> 5;
    if (lane == 0) red[w] = s;
    __syncthreads();
    if (w == 0) {
        s = (lane < 8) ? red[lane] : 0.0f;
        #pragma unroll
        for (int o = 4; o > 0; o >>= 1) s += __shfl_down_sync(0xffffffffu, s, o);
        if (lane == 0) g_d[row] = rsqrtf(s + 1.0f);
    }
}

// ---------------------------------------------------------------------------
// Kernel 2: g_supp = d_m * (input @ weight), TF32 tensor version.
// CTA 128x256 (full N), 8 warps (64x64), K=256 (4 stages of KT=64),
// 2-stage double buffer, one barrier per stage. Grid = 64 CTAs.
// ---------------------------------------------------------------------------
__global__ __launch_bounds__(256, 1)
void supp_gemm_kernel(const float* __restrict__ input,
                      const float* __restrict__ weight) {
    extern __shared__ float smem[];
    const uint32_t sb_u32 = smem_to_u32(smem);

    const int tid = threadIdx.x;
    const int wid = tid >> 5;
    const int lane = tid & 31;
    const int gid = lane >> 2;
    const int tig = lane & 3;
    const int wm = wid >> 2;        // 0..1
    const int wn = wid & 3;         // 0..3

    const int mBase = blockIdx.x * 128;
    const float* Abase = input + (size_t)mBase * FEAT;

    float acc[4][8][4];
    #pragma unroll
    for (int mt = 0; mt < 4; mt++)
        #pragma unroll
        for (int nt = 0; nt < 8; nt++)
            #pragma unroll
            for (int c = 0; c < 4; c++) acc[mt][nt][c] = 0.0f;

    auto load_stage = [&](int s) {
        const int slot = s & 1;
        const uint32_t a_s = sb_u32 + slot * STAGE_BYTES;
        const uint32_t b_s = a_s + 128 * SA * 4;
        const float* ag = Abase + s * KT;
        const float* bg = weight + (size_t)(s * KT) * FEAT;
        #pragma unroll
        for (int i = 0; i < 8; i++) {            // A: 128r x 64k
            const int g = tid + i * 256;
            const int r = g >> 4, q = g & 15;
            CP_ASYNC_CG(a_s + (r * SA + q * 4) * 4, ag + (size_t)r * FEAT + q * 4);
        }
        #pragma unroll
        for (int i = 0; i < 16; i++) {           // B: 64k x 256n
            const int g = tid + i * 256;
            const int k = g >> 6, q = g & 63;
            CP_ASYNC_CG(b_s + (k * SB + q * 4) * 4, bg + (size_t)k * FEAT + q * 4);
        }
    };

    load_stage(0); CP_COMMIT();

    const int NIT = FEAT / KT;   // 4
    for (int s = 0; s < NIT; s++) {
        CP_WAIT0();
        __syncthreads();
        if (s + 1 < NIT) { load_stage(s + 1); CP_COMMIT(); }

        const float* As = smem + (s & 1) * STAGE_FLOATS;
        const float* Bs = As + 128 * SA;

        #pragma unroll
        for (int k8 = 0; k8 < KT / 8; k8++) {
            const int kk = k8 * 8;
            uint32_t a[4][4], b[8][2];
            #pragma unroll
            for (int mt = 0; mt < 4; mt++) {
                const int r = wm * 64 + mt * 16 + gid;
                a[mt][0] = __float_as_uint(As[r * SA + kk + tig]);
                a[mt][1] = __float_as_uint(As[(r + 8) * SA + kk + tig]);
                a[mt][2] = __float_as_uint(As[r * SA + kk + tig + 4]);
                a[mt][3] = __float_as_uint(As[(r + 8) * SA + kk + tig + 4]);
            }
            #pragma unroll
            for (int nt = 0; nt < 8; nt++) {
                const int n = wn * 64 + nt * 8 + gid;
                b[nt][0] = __float_as_uint(Bs[(kk + tig) * SB + n]);
                b[nt][1] = __float_as_uint(Bs[(kk + tig + 4) * SB + n]);
            }
            #pragma unroll
            for (int mt = 0; mt < 4; mt++)
                #pragma unroll
                for (int nt = 0; nt < 8; nt++)
                    mma_tf32(acc[mt][nt], a[mt], b[nt]);
        }
    }

    // epilogue: g_supp[r][n] = d_r * acc
    #pragma unroll
    for (int mt = 0; mt < 4; mt++) {
        const int r0 = mBase + wm * 64 + mt * 16 + gid;
        const int r1 = r0 + 8;
        const float d0 = g_d[r0];
        const float d1 = g_d[r1];
        #pragma unroll
        for (int nt = 0; nt < 8; nt++) {
            const int col = wn * 64 + nt * 8 + tig * 2;
            float2 o0, o1;
            o0.x = d0 * acc[mt][nt][0]; o0.y = d0 * acc[mt][nt][1];
            o1.x = d1 * acc[mt][nt][2]; o1.y = d1 * acc[mt][nt][3];
            *reinterpret_cast<float2*>(g_supp + (size_t)r0 * FEAT + col) = o0;
            *reinterpret_cast<float2*>(g_supp + (size_t)r1 * FEAT + col) = o1;
        }
    }
}

// ---------------------------------------------------------------------------
// Kernel 3: partial[split] = adj[:, kr] @ suppd[kr, :]   (R11 version)
// TF32 mma.sync m16n8k8, CTA 128x256, 8 warps (64x64), split-K=2, KT=64,
// 2-stage double buffer, one barrier/stage, scalar-LDS fragments, raw-bit tf32.
// ---------------------------------------------------------------------------
#define KSPLIT (N_NODES / 2)                   // 4096
#define NITER (KSPLIT / KT)                    // 64

__global__ __launch_bounds__(256, 1)
void gcn_main_gemm(const float* __restrict__ adj) {
    extern __shared__ float smem[];
    const uint32_t sb_u32 = smem_to_u32(smem);

    const int tid = threadIdx.x;
    const int wid = tid >> 5;
    const int lane = tid & 31;
    const int gid = lane >> 2;
    const int tig = lane & 3;
    const int wm = wid >> 2;        // 0..1
    const int wn = wid & 3;         // 0..3

    const int mBase = blockIdx.y * 128;
    const int split = blockIdx.x;

    const float* Abase = adj + (size_t)mBase * N_NODES + (size_t)split * KSPLIT;
    const float* Bbase = g_supp + (size_t)(split * KSPLIT) * FEAT;

    float acc[4][8][4];
    #pragma unroll
    for (int mt = 0; mt < 4; mt++)
        #pragma unroll
        for (int nt = 0; nt < 8; nt++)
            #pragma unroll
            for (int c = 0; c < 4; c++) acc[mt][nt][c] = 0.0f;

    auto load_stage = [&](int s) {
        const int slot = s & 1;
        const uint32_t a_s = sb_u32 + slot * STAGE_BYTES;
        const uint32_t b_s = a_s + 128 * SA * 4;
        const float* ag = Abase + s * KT;
        const float* bg = Bbase + (size_t)(s * KT) * FEAT;
        #pragma unroll
        for (int i = 0; i < 8; i++) {            // A: 128r x 64k
            const int g = tid + i * 256;
            const int r = g >> 4, q = g & 15;
            CP_ASYNC_CG(a_s + (r * SA + q * 4) * 4, ag + (size_t)r * N_NODES + q * 4);
        }
        #pragma unroll
        for (int i = 0; i < 16; i++) {           // B: 64k x 256n
            const int g = tid + i * 256;
            const int k = g >> 6, q = g & 63;
            CP_ASYNC_CG(b_s + (k * SB + q * 4) * 4, bg + (size_t)k * FEAT + q * 4);
        }
    };

    load_stage(0); CP_COMMIT();

    for (int s = 0; s < NITER; s++) {
        CP_WAIT0();
        __syncthreads();

        if (s + 1 < NITER) { load_stage(s + 1); CP_COMMIT(); }

        const float* As = smem + (s & 1) * STAGE_FLOATS;
        const float* Bs = As + 128 * SA;

        #pragma unroll
        for (int k8 = 0; k8 < KT / 8; k8++) {
            const int kk = k8 * 8;
            uint32_t a[4][4], b[8][2];
            #pragma unroll
            for (int mt = 0; mt < 4; mt++) {
                const int r = wm * 64 + mt * 16 + gid;
                a[mt][0] = __float_as_uint(As[r * SA + kk + tig]);
                a[mt][1] = __float_as_uint(As[(r + 8) * SA + kk + tig]);
                a[mt][2] = __float_as_uint(As[r * SA + kk + tig + 4]);
                a[mt][3] = __float_as_uint(As[(r + 8) * SA + kk + tig + 4]);
            }
            #pragma unroll
            for (int nt = 0; nt < 8; nt++) {
                const int n = wn * 64 + nt * 8 + gid;
                b[nt][0] = __float_as_uint(Bs[(kk + tig) * SB + n]);
                b[nt][1] = __float_as_uint(Bs[(kk + tig + 4) * SB + n]);
            }
            #pragma unroll
            for (int mt = 0; mt < 4; mt++)
                #pragma unroll
                for (int nt = 0; nt < 8; nt++)
                    mma_tf32(acc[mt][nt], a[mt], b[nt]);
        }
    }

    // write raw partials
    float* dst = g_part + (size_t)split * N_NODES * FEAT;
    #pragma unroll
    for (int mt = 0; mt < 4; mt++) {
        const int r0 = mBase + wm * 64 + mt * 16 + gid;
        const int r1 = r0 + 8;
        #pragma unroll
        for (int nt = 0; nt < 8; nt++) {
            const int col = wn * 64 + nt * 8 + tig * 2;
            float2 o0, o1;
            o0.x = acc[mt][nt][0]; o0.y = acc[mt][nt][1];
            o1.x = acc[mt][nt][2]; o1.y = acc[mt][nt][3];
            *reinterpret_cast<float2*>(dst + (size_t)r0 * FEAT + col) = o0;
            *reinterpret_cast<float2*>(dst + (size_t)r1 * FEAT + col) = o1;
        }
    }
}

// ---------------------------------------------------------------------------
// Kernel 4: fixup  out = d_i*(p0 + p1 + suppd[i,:]) + bias
// ---------------------------------------------------------------------------
__global__ __launch_bounds__(256)
void fixup_kernel(float* __restrict__ out, const float* __restrict__ bias) {
    const size_t i = (size_t)blockIdx.x * 256 + threadIdx.x;
    const size_t row = i >> 6;
    const int c4 = (int)(i & 63);
    const float d = g_d[row];
    const float4 p0 = *reinterpret_cast<const float4*>(g_part + row * FEAT + c4 * 4);
    const float4 p1 = *reinterpret_cast<const float4*>(g_part + (size_t)N_NODES * FEAT + row * FEAT + c4 * 4);
    const float4 sv = *reinterpret_cast<const float4*>(g_supp + row * FEAT + c4 * 4);
    const float4 bv = *reinterpret_cast<const float4*>(bias + c4 * 4);
    float4 o;
    o.x = fmaf(d, p0.x + p1.x + sv.x, bv.x);
    o.y = fmaf(d, p0.y + p1.y + sv.y, bv.y);
    o.z = fmaf(d, p0.z + p1.z + sv.z, bv.z);
    o.w = fmaf(d, p0.w + p1.w + sv.w, bv.w);
    *reinterpret_cast<float4*>(out + row * FEAT + c4 * 4) = o;
}

// ---------------------------------------------------------------------------
extern "C" void kernel_launch(void* const* d_in, const int* in_sizes, int n_in,
                              void* d_out, int out_size) {
    const float* input  = (const float*)d_in[0];   // [8192, 256]
    const float* adj    = (const float*)d_in[1];   // [8192, 8192]
    const float* weight = (const float*)d_in[2];   // [256, 256]
    const float* bias   = (const float*)d_in[3];   // [256]
    float* out = (float*)d_out;

    cudaFuncSetAttribute(supp_gemm_kernel, cudaFuncAttributeMaxDynamicSharedMemorySize, MAIN_SMEM);
    cudaFuncSetAttribute(gcn_main_gemm, cudaFuncAttributeMaxDynamicSharedMemorySize, MAIN_SMEM);

    rowsum_rsqrt_kernel<<<N_NODES, 256>>>(adj);
    supp_gemm_kernel<<<N_NODES / 128, 256, MAIN_SMEM>>>(input, weight);
    {
        dim3 grid(2, N_NODES / 128);   // (split, mtile) = 128 CTAs
        gcn_main_gemm<<<grid, 256, MAIN_SMEM>>>(adj);
    }
    fixup_kernel<<<(N_NODES * FEAT / 4) / 256, 256>>>(out, bias);
}